// round 1
// baseline (speedup 1.0000x reference)
#include <cuda_runtime.h>
#include <cstdint>

// Problem constants
#define BATCH   16
#define C_IN    128
#define C_OUT   3
#define W_DIM   512
#define HW      65536          // 256*256
#define HW4     (HW/4)         // float4 groups per channel plane
#define CONV_CLAMP 256.0f

// Scratch: per-batch effective weights eff[b][i] = {e_o0, e_o1, e_o2, 0}
__device__ float4 d_eff[BATCH][C_IN];

// ---------------------------------------------------------------------------
// Kernel 1: styles + effective-weight precompute.
// grid = BATCH, block = C_IN (128 threads). Thread i computes
//   m_t = (w[b] . affine_w[t*128+i]) * fc_gain + affine_b[t*128+i]
//   style = (m1*m2 + m3) / sqrt(C_IN)
//   eff[b][i][o] = style * weight[o][i]
// ---------------------------------------------------------------------------
__global__ void style_kernel(const float* __restrict__ w,
                             const float* __restrict__ weight,
                             const float* __restrict__ affine_w,
                             const float* __restrict__ affine_b)
{
    const int b = blockIdx.x;
    const int i = threadIdx.x;

    __shared__ float ws[W_DIM];
    for (int k = i; k < W_DIM; k += C_IN)
        ws[k] = w[b * W_DIM + k];
    __syncthreads();

    const float fc_gain = 0.044194173824159216f;  // 1/sqrt(512)
    const float istyle  = 0.08838834764831845f;   // 1/sqrt(128)

    float m[3];
    #pragma unroll
    for (int t = 0; t < 3; ++t) {
        const float4* row = (const float4*)(affine_w + (size_t)(t * C_IN + i) * W_DIM);
        float acc = 0.0f;
        #pragma unroll 8
        for (int k = 0; k < W_DIM / 4; ++k) {
            float4 a = row[k];
            const float4* wv = (const float4*)ws + k;
            acc += a.x * wv->x + a.y * wv->y + a.z * wv->z + a.w * wv->w;
        }
        m[t] = acc * fc_gain + affine_b[t * C_IN + i];
    }

    const float style = (m[0] * m[1] + m[2]) * istyle;

    float4 e;
    e.x = style * weight[0 * C_IN + i];
    e.y = style * weight[1 * C_IN + i];
    e.z = style * weight[2 * C_IN + i];
    e.w = 0.0f;
    d_eff[b][i] = e;
}

// ---------------------------------------------------------------------------
// Kernel 2: streaming 1x1 conv (M=3, K=128) over pixels.
// grid = (HW4/256, BATCH), block = 256. Each thread owns one float4 pixel
// group: loops over 128 channels, one coalesced LDG.128 per channel plane,
// accumulating into 3 float4 accumulators; adds bias, clamps, stores.
// ---------------------------------------------------------------------------
__global__ __launch_bounds__(256)
void conv_kernel(const float* __restrict__ x,
                 const float* __restrict__ bias,
                 float* __restrict__ out)
{
    const int b   = blockIdx.y;
    const int tid = threadIdx.x;

    __shared__ float4 eff_s[C_IN];
    if (tid < C_IN)
        eff_s[tid] = d_eff[b][tid];
    __syncthreads();

    const int g = blockIdx.x * blockDim.x + tid;   // float4 group in [0, HW4)
    const float4* xb = (const float4*)(x + (size_t)b * C_IN * HW) + g;

    float4 a0 = make_float4(0.f, 0.f, 0.f, 0.f);
    float4 a1 = a0;
    float4 a2 = a0;

    #pragma unroll 8
    for (int i = 0; i < C_IN; ++i) {
        const float4 xv = xb[(size_t)i * HW4];
        const float4 e  = eff_s[i];
        a0.x += xv.x * e.x; a0.y += xv.y * e.x; a0.z += xv.z * e.x; a0.w += xv.w * e.x;
        a1.x += xv.x * e.y; a1.y += xv.y * e.y; a1.z += xv.z * e.y; a1.w += xv.w * e.y;
        a2.x += xv.x * e.z; a2.y += xv.y * e.z; a2.z += xv.z * e.z; a2.w += xv.w * e.z;
    }

    const float b0 = __ldg(bias + 0);
    const float b1 = __ldg(bias + 1);
    const float b2 = __ldg(bias + 2);

    #define CLAMP1(v, bb) fminf(fmaxf((v) + (bb), -CONV_CLAMP), CONV_CLAMP)
    float4 o0 = make_float4(CLAMP1(a0.x,b0), CLAMP1(a0.y,b0), CLAMP1(a0.z,b0), CLAMP1(a0.w,b0));
    float4 o1 = make_float4(CLAMP1(a1.x,b1), CLAMP1(a1.y,b1), CLAMP1(a1.z,b1), CLAMP1(a1.w,b1));
    float4 o2 = make_float4(CLAMP1(a2.x,b2), CLAMP1(a2.y,b2), CLAMP1(a2.z,b2), CLAMP1(a2.w,b2));
    #undef CLAMP1

    float4* ob = (float4*)(out + (size_t)b * C_OUT * HW) + g;
    ob[0 * HW4] = o0;
    ob[1 * HW4] = o1;
    ob[2 * HW4] = o2;
}

// ---------------------------------------------------------------------------
// Launch. Input order (metadata): x, w, weight, bias, affine_w, affine_b.
// ---------------------------------------------------------------------------
extern "C" void kernel_launch(void* const* d_in, const int* in_sizes, int n_in,
                              void* d_out, int out_size)
{
    const float* x        = (const float*)d_in[0];
    const float* w        = (const float*)d_in[1];
    const float* weight   = (const float*)d_in[2];
    const float* bias     = (const float*)d_in[3];
    const float* affine_w = (const float*)d_in[4];
    const float* affine_b = (const float*)d_in[5];
    float* out = (float*)d_out;

    style_kernel<<<BATCH, C_IN>>>(w, weight, affine_w, affine_b);

    dim3 grid(HW4 / 256, BATCH);
    conv_kernel<<<grid, 256>>>(x, bias, out);
}

// round 2
// speedup vs baseline: 1.6619x; 1.6619x over previous
#include <cuda_runtime.h>
#include <cstdint>

// Problem constants
#define BATCH   16
#define C_IN    128
#define C_OUT   3
#define W_DIM   512
#define HW      65536          // 256*256
#define HW4     (HW/4)         // float4 groups per channel plane
#define CONV_CLAMP 256.0f

// Scratch: per-batch effective weights eff[b][i] = {e_o0, e_o1, e_o2, 0}
__device__ float4 d_eff[BATCH][C_IN];

// ---------------------------------------------------------------------------
// Kernel 1: styles + effective-weight precompute.
// One WARP per (b, i) output: 16*128 = 2048 warps, 256 blocks x 256 threads.
// Each warp computes the 3 dot products (length 512) with coalesced float4
// loads (lane l reads elements [l*4 + k*128 ..]), shfl-reduces, lane 0 writes
// eff[b][i] = style * weight[:, i].
// ---------------------------------------------------------------------------
__global__ __launch_bounds__(256)
void style_kernel(const float* __restrict__ w,
                  const float* __restrict__ weight,
                  const float* __restrict__ affine_w,
                  const float* __restrict__ affine_b)
{
    const int gwarp = (blockIdx.x * blockDim.x + threadIdx.x) >> 5;
    const int lane  = threadIdx.x & 31;
    const int b = gwarp >> 7;        // / 128
    const int i = gwarp & 127;       // % 128

    const float4* wv = (const float4*)(w + (size_t)b * W_DIM);

    float acc[3];
    #pragma unroll
    for (int t = 0; t < 3; ++t) {
        const float4* row = (const float4*)(affine_w + (size_t)(t * C_IN + i) * W_DIM);
        float a = 0.0f;
        #pragma unroll
        for (int k = 0; k < 4; ++k) {
            const float4 av = row[lane + k * 32];
            const float4 bv = wv[lane + k * 32];
            a += av.x * bv.x + av.y * bv.y + av.z * bv.z + av.w * bv.w;
        }
        acc[t] = a;
    }

    #pragma unroll
    for (int off = 16; off; off >>= 1) {
        acc[0] += __shfl_xor_sync(0xFFFFFFFFu, acc[0], off);
        acc[1] += __shfl_xor_sync(0xFFFFFFFFu, acc[1], off);
        acc[2] += __shfl_xor_sync(0xFFFFFFFFu, acc[2], off);
    }

    if (lane == 0) {
        const float fc_gain = 0.044194173824159216f;  // 1/sqrt(512)
        const float istyle  = 0.08838834764831845f;   // 1/sqrt(128)
        const float m1 = acc[0] * fc_gain + affine_b[0 * C_IN + i];
        const float m2 = acc[1] * fc_gain + affine_b[1 * C_IN + i];
        const float m3 = acc[2] * fc_gain + affine_b[2 * C_IN + i];
        const float style = (m1 * m2 + m3) * istyle;

        float4 e;
        e.x = style * weight[0 * C_IN + i];
        e.y = style * weight[1 * C_IN + i];
        e.z = style * weight[2 * C_IN + i];
        e.w = 0.0f;
        d_eff[b][i] = e;
    }
}

// ---------------------------------------------------------------------------
// Kernel 2: streaming 1x1 conv (M=3, K=128) over pixels.
// grid = (HW4/256, BATCH), block = 256. Each thread owns one float4 pixel
// group. Channel loop processes pairs (i, i+64) for 2x memory-level
// parallelism (16 outstanding LDG.128 with unroll 8). Non-temporal loads
// (x has zero reuse) and streaming stores.
// ---------------------------------------------------------------------------
__global__ __launch_bounds__(256)
void conv_kernel(const float* __restrict__ x,
                 const float* __restrict__ bias,
                 float* __restrict__ out)
{
    const int b   = blockIdx.y;
    const int tid = threadIdx.x;

    __shared__ float4 eff_s[C_IN];
    if (tid < C_IN)
        eff_s[tid] = d_eff[b][tid];
    __syncthreads();

    const int g = blockIdx.x * blockDim.x + tid;   // float4 group in [0, HW4)
    const float4* xa = (const float4*)(x + (size_t)b * C_IN * HW) + g;
    const float4* xc = xa + (size_t)64 * HW4;      // second channel stream

    float4 a0 = make_float4(0.f, 0.f, 0.f, 0.f);
    float4 a1 = a0;
    float4 a2 = a0;

    #pragma unroll 8
    for (int i = 0; i < 64; ++i) {
        const float4 xv0 = __ldcs(xa + (size_t)i * HW4);
        const float4 xv1 = __ldcs(xc + (size_t)i * HW4);
        const float4 e0  = eff_s[i];
        const float4 e1  = eff_s[i + 64];

        a0.x += xv0.x * e0.x; a0.y += xv0.y * e0.x; a0.z += xv0.z * e0.x; a0.w += xv0.w * e0.x;
        a1.x += xv0.x * e0.y; a1.y += xv0.y * e0.y; a1.z += xv0.z * e0.y; a1.w += xv0.w * e0.y;
        a2.x += xv0.x * e0.z; a2.y += xv0.y * e0.z; a2.z += xv0.z * e0.z; a2.w += xv0.w * e0.z;

        a0.x += xv1.x * e1.x; a0.y += xv1.y * e1.x; a0.z += xv1.z * e1.x; a0.w += xv1.w * e1.x;
        a1.x += xv1.x * e1.y; a1.y += xv1.y * e1.y; a1.z += xv1.z * e1.y; a1.w += xv1.w * e1.y;
        a2.x += xv1.x * e1.z; a2.y += xv1.y * e1.z; a2.z += xv1.z * e1.z; a2.w += xv1.w * e1.z;
    }

    const float b0 = __ldg(bias + 0);
    const float b1 = __ldg(bias + 1);
    const float b2 = __ldg(bias + 2);

    #define CLAMP1(v, bb) fminf(fmaxf((v) + (bb), -CONV_CLAMP), CONV_CLAMP)
    float4 o0 = make_float4(CLAMP1(a0.x,b0), CLAMP1(a0.y,b0), CLAMP1(a0.z,b0), CLAMP1(a0.w,b0));
    float4 o1 = make_float4(CLAMP1(a1.x,b1), CLAMP1(a1.y,b1), CLAMP1(a1.z,b1), CLAMP1(a1.w,b1));
    float4 o2 = make_float4(CLAMP1(a2.x,b2), CLAMP1(a2.y,b2), CLAMP1(a2.z,b2), CLAMP1(a2.w,b2));
    #undef CLAMP1

    float4* ob = (float4*)(out + (size_t)b * C_OUT * HW) + g;
    __stcs(ob + 0 * HW4, o0);
    __stcs(ob + 1 * HW4, o1);
    __stcs(ob + 2 * HW4, o2);
}

// ---------------------------------------------------------------------------
// Launch. Input order (metadata): x, w, weight, bias, affine_w, affine_b.
// ---------------------------------------------------------------------------
extern "C" void kernel_launch(void* const* d_in, const int* in_sizes, int n_in,
                              void* d_out, int out_size)
{
    const float* x        = (const float*)d_in[0];
    const float* w        = (const float*)d_in[1];
    const float* weight   = (const float*)d_in[2];
    const float* bias     = (const float*)d_in[3];
    const float* affine_w = (const float*)d_in[4];
    const float* affine_b = (const float*)d_in[5];
    float* out = (float*)d_out;

    // 2048 warps = one per (batch, channel) output; 256 blocks x 256 threads
    style_kernel<<<(BATCH * C_IN * 32) / 256, 256>>>(w, weight, affine_w, affine_b);

    dim3 grid(HW4 / 256, BATCH);
    conv_kernel<<<grid, 256>>>(x, bias, out);
}